// round 2
// baseline (speedup 1.0000x reference)
#include <cuda_runtime.h>
#include <cstdint>

#define BB 32
#define HH 128
#define WW 128
#define NPIX 16384            // 128*128
#define WIDTH 64
#define M1 20
#define M2 20

// ---------------- scratch (device globals; no runtime allocation) ----------------
__device__ float g_x [ (size_t)BB*WIDTH*NPIX ];   // current state (B,64,H,W)
__device__ float g_x1[ (size_t)BB*WIDTH*NPIX ];   // spectral branch out
__device__ float g_x2[ (size_t)BB*WIDTH*NPIX ];   // conv branch out
__device__ float g_y1[ (size_t)BB*WIDTH*128*40 ]; // fwd W-DFT: (b,c,h, [20 re | 20 im])
__device__ float g_z [ (size_t)BB*WIDTH*1600 ];   // fwd H-DFT: (b,c, [800 re | 800 im]) over (kx40,ky20)
__device__ float g_zo[ (size_t)BB*WIDTH*1600 ];   // after mode mixing
__device__ float g_u [ (size_t)BB*WIDTH*5120 ];   // inv H: (b,o,h,[20 re|20 im])
__device__ float g_Tf [40*128];                   // rows 0..19: cos(2pi w k/128); 20..39: -sin
__device__ float g_ThC[40*128];                   // cos(2pi h kx/128), kx in {0..19,108..127}
__device__ float g_ThS[40*128];                   // sin(...)

__device__ __forceinline__ float gelu_t(float x) {
    // jax.nn.gelu default (approximate=True, tanh form)
    float x3 = x * x * x;
    return 0.5f * x * (1.0f + tanhf(0.7978845608028654f * (x + 0.044715f * x3)));
}

// ---------------- twiddle tables ----------------
__global__ void k_init_tables() {
    for (int i = threadIdx.x + blockIdx.x * blockDim.x; i < 40 * 128; i += blockDim.x * gridDim.x) {
        int k = i / 128, w = i % 128;
        float s, c;
        if (k < 20) {
            sincospif((float)((w * k) & 127) / 64.0f, &s, &c);
            g_Tf[i] = c;
        } else {
            sincospif((float)((w * (k - 20)) & 127) / 64.0f, &s, &c);
            g_Tf[i] = -s;
        }
        int kxv = (k < 20) ? k : (108 + (k - 20));
        sincospif((float)((w * kxv) & 127) / 64.0f, &s, &c);
        g_ThC[i] = c;
        g_ThS[i] = s;
    }
}

// ---------------- lift: grid + quadpath + fc0 MLP -> g_x (B,64,H,W) ----------------
__global__ void __launch_bounds__(128) k_lift(
    const float* __restrict__ xin, const float* __restrict__ qa, const float* __restrict__ qb,
    const float* __restrict__ w1, const float* __restrict__ b1,
    const float* __restrict__ w2, const float* __restrict__ b2)
{
    __shared__ float qas[48], qbs[48], b2s[48];
    __shared__ float w1s[128 * 16];
    __shared__ float b1s[128];
    __shared__ float w2t[128 * 48];  // transposed: [m][o]
    int tid = threadIdx.x;
    if (tid < 48) { qas[tid] = qa[tid]; qbs[tid] = qb[tid]; b2s[tid] = b2[tid]; }
    b1s[tid] = b1[tid];
    for (int i = tid; i < 2048; i += 128) w1s[i] = w1[i];
    for (int i = tid; i < 6144; i += 128) { int o = i / 128, m = i % 128; w2t[m * 48 + o] = w2[i]; }
    __syncthreads();

    int p = blockIdx.x * 128 + tid;
    int b = p >> 14, pix = p & 16383;
    int h = pix >> 7, w = pix & 127;

    float f[16];
    const float* xp = xin + ((size_t)b * 10) * NPIX + pix;
#pragma unroll
    for (int c = 0; c < 10; c++) f[c] = xp[(size_t)c * NPIX];
    f[10] = (float)h * (1.0f / 127.0f);
    f[11] = (float)w * (1.0f / 127.0f);
#pragma unroll
    for (int j = 0; j < 4; j++) {
        float sa = 0.f, sb = 0.f;
#pragma unroll
        for (int c = 0; c < 12; c++) { sa += qas[j * 12 + c] * f[c]; sb += qbs[j * 12 + c] * f[c]; }
        f[12 + j] = sa * sb;
    }
    float acc[48];
#pragma unroll
    for (int o = 0; o < 48; o++) acc[o] = b2s[o];
    for (int m = 0; m < 128; m++) {
        float t = b1s[m];
#pragma unroll
        for (int c = 0; c < 16; c++) t += w1s[m * 16 + c] * f[c];
        float g = gelu_t(t);
#pragma unroll
        for (int o4 = 0; o4 < 12; o4++) {
            float4 wv = *(const float4*)&w2t[m * 48 + o4 * 4];
            acc[o4 * 4 + 0] += wv.x * g; acc[o4 * 4 + 1] += wv.y * g;
            acc[o4 * 4 + 2] += wv.z * g; acc[o4 * 4 + 3] += wv.w * g;
        }
    }
    float* op = g_x + ((size_t)b * WIDTH) * NPIX + pix;
#pragma unroll
    for (int c = 0; c < 16; c++) op[(size_t)c * NPIX] = f[c];
#pragma unroll
    for (int o = 0; o < 48; o++) op[(size_t)(16 + o) * NPIX] = acc[o];
}

// ---------------- forward partial rfft along W ----------------
// rows: (b,c,h) flattened = 262144.  out[row][k<20]=Re, [20..39]=Im
__global__ void __launch_bounds__(256) k_fwdW() {
    __shared__ float xs[32][128];
    __shared__ float tf[128][40];
    int row0 = blockIdx.x * 32;
    for (int i = threadIdx.x; i < 32 * 128; i += 256)
        xs[i / 128][i % 128] = g_x[(size_t)row0 * 128 + i];
    for (int i = threadIdx.x; i < 40 * 128; i += 256) {
        int k = i / 128, w = i % 128;
        tf[w][k] = g_Tf[i];
    }
    __syncthreads();
    for (int u = threadIdx.x; u < 320; u += 256) {
        int r = u / 10, kg = (u % 10) * 4;
        float s0 = 0.f, s1 = 0.f, s2 = 0.f, s3 = 0.f;
#pragma unroll 8
        for (int w = 0; w < 128; w++) {
            float xv = xs[r][w];
            float4 t = *(const float4*)&tf[w][kg];
            s0 += xv * t.x; s1 += xv * t.y; s2 += xv * t.z; s3 += xv * t.w;
        }
        float4 o; o.x = s0; o.y = s1; o.z = s2; o.w = s3;
        *(float4*)&g_y1[(size_t)(row0 + r) * 40 + kg] = o;
    }
}

// ---------------- forward full DFT along H at the 40 kept kx ----------------
__global__ void __launch_bounds__(256) k_fwdH() {
    __shared__ float ys[128][40];
    int bc = blockIdx.x;
    const float* src = g_y1 + (size_t)bc * 5120;
    for (int i = threadIdx.x; i < 5120; i += 256) ys[i / 40][i % 40] = src[i];
    __syncthreads();
    for (int o = threadIdx.x; o < 800; o += 256) {
        int kx = o / 20, ky = o % 20;
        float zr = 0.f, zi = 0.f;
#pragma unroll 4
        for (int h = 0; h < 128; h++) {
            float c = g_ThC[kx * 128 + h], s = g_ThS[kx * 128 + h];
            float yr = ys[h][ky], yi = ys[h][20 + ky];
            zr += yr * c + yi * s;
            zi += yi * c - yr * s;
        }
        g_z[(size_t)bc * 1600 + o] = zr;
        g_z[(size_t)bc * 1600 + 800 + o] = zi;
    }
}

// ---------------- per-mode complex channel mixing ----------------
__global__ void __launch_bounds__(256) k_mix(
    const float* __restrict__ sw1r, const float* __restrict__ sw1i,
    const float* __restrict__ sw2r, const float* __restrict__ sw2i, int layer)
{
    __shared__ float Wr[64][64], Wi[64][64];
    __shared__ float Zr[4][64], Zi[4][64];
    int m = blockIdx.x;
    int kxi = m / 20, ky = m % 20;
    const float* wr; const float* wi; int kxm;
    if (kxi < 20) { wr = sw1r; wi = sw1i; kxm = kxi; }
    else          { wr = sw2r; wi = sw2i; kxm = kxi - 20; }
    size_t base = (size_t)layer * 64 * 64 * 400;
    for (int i = threadIdx.x; i < 4096; i += 256) {
        int ii = i / 64, oo = i % 64;
        size_t idx = base + (size_t)(ii * 64 + oo) * 400 + kxm * 20 + ky;
        Wr[ii][oo] = wr[idx]; Wi[ii][oo] = wi[idx];
    }
    int oo = threadIdx.x & 63, bb = threadIdx.x >> 6;
    for (int b0 = 0; b0 < 32; b0 += 4) {
        __syncthreads();
        for (int i = threadIdx.x; i < 256; i += 256) {
            int lb = i / 64, c = i % 64;
            size_t zb = ((size_t)(b0 + lb) * 64 + c) * 1600 + kxi * 20 + ky;
            Zr[lb][c] = g_z[zb]; Zi[lb][c] = g_z[zb + 800];
        }
        __syncthreads();
        float orr = 0.f, oii = 0.f;
#pragma unroll 8
        for (int i2 = 0; i2 < 64; i2++) {
            float zr = Zr[bb][i2], zi = Zi[bb][i2];
            float wrv = Wr[i2][oo], wiv = Wi[i2][oo];
            orr += zr * wrv - zi * wiv;
            oii += zr * wiv + zi * wrv;
        }
        size_t ob = ((size_t)(b0 + bb) * 64 + oo) * 1600 + kxi * 20 + ky;
        g_zo[ob] = orr; g_zo[ob + 800] = oii;
    }
}

// ---------------- inverse DFT along H (unnormalized) ----------------
__global__ void __launch_bounds__(256) k_invH() {
    __shared__ float zs[1600];
    int bo = blockIdx.x;
    for (int i = threadIdx.x; i < 1600; i += 256) zs[i] = g_zo[(size_t)bo * 1600 + i];
    __syncthreads();
    for (int o = threadIdx.x; o < 2560; o += 256) {
        int h = o / 20, ky = o % 20;
        float ur = 0.f, ui = 0.f;
#pragma unroll 8
        for (int kx = 0; kx < 40; kx++) {
            float c = g_ThC[kx * 128 + h], s = g_ThS[kx * 128 + h];
            float zr = zs[kx * 20 + ky], zi = zs[800 + kx * 20 + ky];
            ur += zr * c - zi * s;
            ui += zr * s + zi * c;
        }
        g_u[(size_t)bo * 5120 + h * 40 + ky]      = ur;
        g_u[(size_t)bo * 5120 + h * 40 + 20 + ky] = ui;
    }
}

// ---------------- inverse rfft along W, scale 1/(H*W) ----------------
__global__ void __launch_bounds__(256) k_invW() {
    __shared__ float us[128][40];
    __shared__ float tfs[40][128];
    int bo = blockIdx.x;
    for (int i = threadIdx.x; i < 5120; i += 256) us[i / 40][i % 40] = g_u[(size_t)bo * 5120 + i];
    for (int i = threadIdx.x; i < 40 * 128; i += 256) ((float*)tfs)[i] = g_Tf[i];
    __syncthreads();
    const float inv = 1.0f / 16384.0f;
    for (int u = threadIdx.x; u < 4096; u += 256) {
        int h = u >> 5, w4 = (u & 31) * 4;
        float a0 = 0.f, a1 = 0.f, a2 = 0.f, a3 = 0.f;
#pragma unroll
        for (int ky = 1; ky < 20; ky++) {
            float ur = us[h][ky], ui = us[h][20 + ky];
            float4 c4 = *(const float4*)&tfs[ky][w4];
            float4 s4 = *(const float4*)&tfs[20 + ky][w4];
            a0 += ur * c4.x + ui * s4.x;
            a1 += ur * c4.y + ui * s4.y;
            a2 += ur * c4.z + ui * s4.z;
            a3 += ur * c4.w + ui * s4.w;
        }
        float dc = us[h][0];  // ky=0: imag part dropped by C2R
        float4 o;
        o.x = (dc + 2.f * a0) * inv;
        o.y = (dc + 2.f * a1) * inv;
        o.z = (dc + 2.f * a2) * inv;
        o.w = (dc + 2.f * a3) * inv;
        *(float4*)&g_x1[(size_t)bo * NPIX + h * 128 + w4] = o;
    }
}

// ---------------- circular 3x3 conv ----------------
__global__ void __launch_bounds__(256) k_conv(
    const float* __restrict__ cw, const float* __restrict__ cb, int layer)
{
    __shared__ float tile[18][18];
    __shared__ float wshT[9][16];
    int b = blockIdx.z >> 2, ocg = blockIdx.z & 3;
    int h0 = blockIdx.y * 16, w0 = blockIdx.x * 16;
    int tx = threadIdx.x, ty = threadIdx.y;
    int tid = ty * 16 + tx;
    float acc[16];
#pragma unroll
    for (int j = 0; j < 16; j++) acc[j] = cb[layer * 64 + ocg * 16 + j];
    const float* xin = g_x + (size_t)b * WIDTH * NPIX;
    for (int cin = 0; cin < 64; cin++) {
        __syncthreads();
        for (int i = tid; i < 324; i += 256) {
            int r = i / 18, cc = i % 18;
            int gh = (h0 + r - 1) & 127, gw = (w0 + cc - 1) & 127;
            tile[r][cc] = xin[(size_t)cin * NPIX + gh * 128 + gw];
        }
        if (tid < 144) {
            int k = tid / 16, j = tid % 16;
            wshT[k][j] = cw[(((size_t)layer * 64 + ocg * 16 + j) * 64 + cin) * 9 + k];
        }
        __syncthreads();
        float v[9];
#pragma unroll
        for (int dy = 0; dy < 3; dy++)
#pragma unroll
            for (int dx = 0; dx < 3; dx++) v[dy * 3 + dx] = tile[ty + dy][tx + dx];
#pragma unroll
        for (int k = 0; k < 9; k++) {
            float vk = v[k];
#pragma unroll
            for (int j4 = 0; j4 < 4; j4++) {
                float4 wv = *(const float4*)&wshT[k][j4 * 4];
                acc[j4 * 4 + 0] += wv.x * vk; acc[j4 * 4 + 1] += wv.y * vk;
                acc[j4 * 4 + 2] += wv.z * vk; acc[j4 * 4 + 3] += wv.w * vk;
            }
        }
    }
    size_t outb = ((size_t)b * 64 + ocg * 16) * NPIX + (h0 + ty) * 128 + (w0 + tx);
#pragma unroll
    for (int j = 0; j < 16; j++) g_x2[outb + (size_t)j * NPIX] = acc[j];
}

// ---------------- product features + pointwise mix + tanh residual ----------------
__global__ void __launch_bounds__(128) k_combine(
    const float* __restrict__ pw, const float* __restrict__ pb, int layer)
{
    __shared__ float ws[64 * 132];  // padded stride 132 for float4 alignment
    __shared__ float bs[64];
    int tid = threadIdx.x;
    for (int i = tid; i < 64 * 130; i += 128) { int o = i / 130, c = i % 130; ws[o * 132 + c] = pw[(size_t)layer * 8320 + i]; }
    if (tid < 64) bs[tid] = pb[layer * 64 + tid];
    __syncthreads();
    int p = blockIdx.x * 128 + tid;
    int b = p >> 14, pix = p & 16383;
    const float* x1p = g_x1 + ((size_t)b * 64) * NPIX + pix;
    const float* x2p = g_x2 + ((size_t)b * 64) * NPIX + pix;
    float acc[64];
#pragma unroll
    for (int o = 0; o < 64; o++) acc[o] = bs[o];
    float sa0 = 0.f, sa1 = 0.f, sa2 = 0.f, sa3 = 0.f;
    for (int c4 = 0; c4 < 64; c4 += 4) {
        float a0 = x1p[(size_t)(c4 + 0) * NPIX], a1 = x1p[(size_t)(c4 + 1) * NPIX];
        float a2 = x1p[(size_t)(c4 + 2) * NPIX], a3 = x1p[(size_t)(c4 + 3) * NPIX];
        float d0 = x2p[(size_t)(c4 + 0) * NPIX], d1 = x2p[(size_t)(c4 + 1) * NPIX];
        float d2 = x2p[(size_t)(c4 + 2) * NPIX], d3 = x2p[(size_t)(c4 + 3) * NPIX];
        if (c4 == 0) { sa0 = a0; sa1 = a1; sa2 = a2; sa3 = a3; }
#pragma unroll
        for (int o = 0; o < 64; o++) {
            float4 wa = *(const float4*)&ws[o * 132 + c4];
            float4 wd = *(const float4*)&ws[o * 132 + 64 + c4];
            acc[o] += wa.x * a0 + wa.y * a1 + wa.z * a2 + wa.w * a3
                    + wd.x * d0 + wd.y * d1 + wd.z * d2 + wd.w * d3;
        }
    }
    float p0 = sa0 * sa2, p1 = sa1 * sa3;
    float* xp = g_x + ((size_t)b * 64) * NPIX + pix;
#pragma unroll
    for (int o = 0; o < 64; o++) {
        float t = acc[o] + ws[o * 132 + 128] * p0 + ws[o * 132 + 129] * p1;
        xp[(size_t)o * NPIX] += tanhf(t);
    }
}

// ---------------- final projection MLP ----------------
__global__ void __launch_bounds__(128) k_final(
    const float* __restrict__ w1, const float* __restrict__ b1,
    const float* __restrict__ w2, const float* __restrict__ b2,
    float* __restrict__ out)
{
    __shared__ float w1s[128 * 64];
    __shared__ float b1s[128], w2s[128];
    int tid = threadIdx.x;
    for (int i = tid; i < 8192; i += 128) w1s[i] = w1[i];
    b1s[tid] = b1[tid];
    w2s[tid] = w2[tid];
    __syncthreads();
    int p = blockIdx.x * 128 + tid;
    int b = p >> 14, pix = p & 16383;
    const float* xp = g_x + ((size_t)b * 64) * NPIX + pix;
    float xv[64];
#pragma unroll
    for (int c = 0; c < 64; c++) xv[c] = xp[(size_t)c * NPIX];
    float acc = b2[0];
    for (int m = 0; m < 128; m++) {
        float t = b1s[m];
#pragma unroll
        for (int c4 = 0; c4 < 16; c4++) {
            float4 wv = *(const float4*)&w1s[m * 64 + c4 * 4];
            t += wv.x * xv[c4 * 4] + wv.y * xv[c4 * 4 + 1] + wv.z * xv[c4 * 4 + 2] + wv.w * xv[c4 * 4 + 3];
        }
        acc += w2s[m] * gelu_t(t);
    }
    out[p] = acc;
}

// ---------------- launch ----------------
extern "C" void kernel_launch(void* const* d_in, const int* in_sizes, int n_in,
                              void* d_out, int out_size)
{
    const float* x      = (const float*)d_in[0];
    const float* qa     = (const float*)d_in[1];
    const float* qb     = (const float*)d_in[2];
    const float* fc0_w1 = (const float*)d_in[3];
    const float* fc0_b1 = (const float*)d_in[4];
    const float* fc0_w2 = (const float*)d_in[5];
    const float* fc0_b2 = (const float*)d_in[6];
    const float* sw1r   = (const float*)d_in[7];
    const float* sw1i   = (const float*)d_in[8];
    const float* sw2r   = (const float*)d_in[9];
    const float* sw2i   = (const float*)d_in[10];
    const float* cw     = (const float*)d_in[11];
    const float* cb     = (const float*)d_in[12];
    const float* pw     = (const float*)d_in[13];
    const float* pb     = (const float*)d_in[14];
    const float* fc1_w1 = (const float*)d_in[15];
    const float* fc1_b1 = (const float*)d_in[16];
    const float* fc1_w2 = (const float*)d_in[17];
    const float* fc1_b2 = (const float*)d_in[18];
    float* out = (float*)d_out;

    k_init_tables<<<20, 256>>>();
    k_lift<<<4096, 128>>>(x, qa, qb, fc0_w1, fc0_b1, fc0_w2, fc0_b2);

    for (int layer = 0; layer < 4; layer++) {
        k_fwdW<<<8192, 256>>>();
        k_fwdH<<<2048, 256>>>();
        k_mix<<<800, 256>>>(sw1r, sw1i, sw2r, sw2i, layer);
        k_invH<<<2048, 256>>>();
        k_invW<<<2048, 256>>>();
        k_conv<<<dim3(8, 8, 128), dim3(16, 16)>>>(cw, cb, layer);
        k_combine<<<4096, 128>>>(pw, pb, layer);
    }

    k_final<<<4096, 128>>>(fc1_w1, fc1_b1, fc1_w2, fc1_b2, out);
}

// round 3
// speedup vs baseline: 1.3642x; 1.3642x over previous
#include <cuda_runtime.h>
#include <cstdint>

#define BB 32
#define NPIX 16384
#define WIDTH 64

typedef unsigned long long u64;

__device__ __forceinline__ u64 pk(float lo, float hi) {
    u64 r; asm("mov.b64 %0, {%1, %2};" : "=l"(r) : "f"(lo), "f"(hi)); return r;
}
__device__ __forceinline__ u64 pk2(float v) {
    u64 r; asm("mov.b64 %0, {%1, %1};" : "=l"(r) : "f"(v)); return r;
}
__device__ __forceinline__ void fma2(u64& d, u64 a, u64 b) {
    asm("fma.rn.f32x2 %0, %1, %2, %0;" : "+l"(d) : "l"(a), "l"(b));
}
__device__ __forceinline__ void unpk(u64 v, float& lo, float& hi) {
    asm("mov.b64 {%0, %1}, %2;" : "=f"(lo), "=f"(hi) : "l"(v));
}

// ---------------- scratch ----------------
__device__ float g_x [ (size_t)BB*WIDTH*NPIX ];
__device__ float g_x1[ (size_t)BB*WIDTH*NPIX ];
__device__ float g_x2[ (size_t)BB*WIDTH*NPIX ];
__device__ float g_y1[ (size_t)BB*WIDTH*5120 ];
__device__ float g_z [ (size_t)BB*WIDTH*1600 ];
__device__ float g_zo[ (size_t)BB*WIDTH*1600 ];
__device__ float g_u [ (size_t)BB*WIDTH*5120 ];
__device__ float g_Tf [40*128];
__device__ float g_ThC[40*128];
__device__ float g_ThS[40*128];

__device__ __forceinline__ float gelu_t(float x) {
    float x3 = x * x * x;
    return 0.5f * x * (1.0f + tanhf(0.7978845608028654f * (x + 0.044715f * x3)));
}

__global__ void k_init_tables() {
    for (int i = threadIdx.x + blockIdx.x * blockDim.x; i < 40 * 128; i += blockDim.x * gridDim.x) {
        int k = i / 128, w = i % 128;
        float s, c;
        if (k < 20) { sincospif((float)((w * k) & 127) / 64.0f, &s, &c); g_Tf[i] = c; }
        else        { sincospif((float)((w * (k - 20)) & 127) / 64.0f, &s, &c); g_Tf[i] = -s; }
        int kxv = (k < 20) ? k : (108 + (k - 20));
        sincospif((float)((w * kxv) & 127) / 64.0f, &s, &c);
        g_ThC[i] = c;
        g_ThS[i] = s;
    }
}

// ---------------- lift ----------------
__global__ void __launch_bounds__(128) k_lift(
    const float* __restrict__ xin, const float* __restrict__ qa, const float* __restrict__ qb,
    const float* __restrict__ w1, const float* __restrict__ b1,
    const float* __restrict__ w2, const float* __restrict__ b2)
{
    __shared__ float qas[48], qbs[48], b2s[48];
    __shared__ __align__(16) float w1s[128 * 16];
    __shared__ float b1s[128];
    __shared__ __align__(16) float w2t[128 * 48];
    int tid = threadIdx.x;
    if (tid < 48) { qas[tid] = qa[tid]; qbs[tid] = qb[tid]; b2s[tid] = b2[tid]; }
    b1s[tid] = b1[tid];
    for (int i = tid; i < 2048; i += 128) w1s[i] = w1[i];
    for (int i = tid; i < 6144; i += 128) { int o = i / 128, m = i % 128; w2t[m * 48 + o] = w2[i]; }
    __syncthreads();
    int p = blockIdx.x * 128 + tid;
    int b = p >> 14, pix = p & 16383;
    int h = pix >> 7, w = pix & 127;
    float f[16];
    const float* xp = xin + ((size_t)b * 10) * NPIX + pix;
#pragma unroll
    for (int c = 0; c < 10; c++) f[c] = xp[(size_t)c * NPIX];
    f[10] = (float)h * (1.0f / 127.0f);
    f[11] = (float)w * (1.0f / 127.0f);
#pragma unroll
    for (int j = 0; j < 4; j++) {
        float sa = 0.f, sb = 0.f;
#pragma unroll
        for (int c = 0; c < 12; c++) { sa += qas[j * 12 + c] * f[c]; sb += qbs[j * 12 + c] * f[c]; }
        f[12 + j] = sa * sb;
    }
    u64 acc2[24];
#pragma unroll
    for (int q = 0; q < 24; q++) acc2[q] = pk(b2s[2 * q], b2s[2 * q + 1]);
    for (int m = 0; m < 128; m++) {
        float t = b1s[m];
#pragma unroll
        for (int c = 0; c < 16; c++) t += w1s[m * 16 + c] * f[c];
        u64 g2 = pk2(gelu_t(t));
        const float* wr = &w2t[m * 48];
#pragma unroll
        for (int q4 = 0; q4 < 12; q4++) {
            ulonglong2 wv = *(const ulonglong2*)&wr[q4 * 4];
            fma2(acc2[q4 * 2], wv.x, g2);
            fma2(acc2[q4 * 2 + 1], wv.y, g2);
        }
    }
    float* op = g_x + ((size_t)b * WIDTH) * NPIX + pix;
#pragma unroll
    for (int c = 0; c < 16; c++) op[(size_t)c * NPIX] = f[c];
#pragma unroll
    for (int q = 0; q < 24; q++) {
        float lo, hi; unpk(acc2[q], lo, hi);
        op[(size_t)(16 + 2 * q) * NPIX] = lo;
        op[(size_t)(17 + 2 * q) * NPIX] = hi;
    }
}

// ---------------- fwd rfft along W: 32 rows/block, 2 rows/thread ----------------
__global__ void __launch_bounds__(160) k_fwdW() {
    __shared__ __align__(16) float xs[128 * 34];   // [w][r], pad 34
    __shared__ __align__(16) float tf4[128 * 40];  // [w][k]
    int tid = threadIdx.x;
    int row0 = blockIdx.x * 32;
    for (int i = tid; i < 4096; i += 160) {
        int r = i >> 7, w = i & 127;
        xs[w * 34 + r] = g_x[(size_t)row0 * 128 + i];
    }
    for (int i = tid; i < 5120; i += 160) {
        int k = i >> 7, w = i & 127;
        tf4[w * 40 + k] = g_Tf[i];
    }
    __syncthreads();
    int rp = tid / 10, kg = (tid % 10) * 4;
    float4 a0 = {0,0,0,0}, a1 = {0,0,0,0};
#pragma unroll 4
    for (int w = 0; w < 128; w++) {
        float2 xv = *(const float2*)&xs[w * 34 + 2 * rp];
        float4 t = *(const float4*)&tf4[w * 40 + kg];
        a0.x += t.x * xv.x; a0.y += t.y * xv.x; a0.z += t.z * xv.x; a0.w += t.w * xv.x;
        a1.x += t.x * xv.y; a1.y += t.y * xv.y; a1.z += t.z * xv.y; a1.w += t.w * xv.y;
    }
    *(float4*)&g_y1[(size_t)(row0 + 2 * rp) * 40 + kg] = a0;
    *(float4*)&g_y1[(size_t)(row0 + 2 * rp + 1) * 40 + kg] = a1;
}

// ---------------- fwd DFT along H (tw in shared, y via ldg broadcast) ----------------
__global__ void __launch_bounds__(256) k_fwdH() {
    __shared__ __align__(16) float2 tw[40 * 130];
    int tid = threadIdx.x;
    int bc = blockIdx.x;
    for (int i = tid; i < 5120; i += 256) {
        int k = i >> 7, w = i & 127;
        tw[k * 130 + w] = make_float2(g_ThC[i], g_ThS[i]);
    }
    __syncthreads();
    if (tid < 200) {
        int kx = tid / 5, kyg = (tid % 5) * 4;
        const float* yb = g_y1 + (size_t)bc * 5120;
        float4 zr = {0,0,0,0}, zi = {0,0,0,0};
#pragma unroll 4
        for (int h = 0; h < 128; h++) {
            float2 cs = tw[kx * 130 + h];
            float4 yr = __ldg((const float4*)&yb[h * 40 + kyg]);
            float4 yi = __ldg((const float4*)&yb[h * 40 + 20 + kyg]);
            zr.x += yr.x * cs.x + yi.x * cs.y;  zi.x += yi.x * cs.x - yr.x * cs.y;
            zr.y += yr.y * cs.x + yi.y * cs.y;  zi.y += yi.y * cs.x - yr.y * cs.y;
            zr.z += yr.z * cs.x + yi.z * cs.y;  zi.z += yi.z * cs.x - yr.z * cs.y;
            zr.w += yr.w * cs.x + yi.w * cs.y;  zi.w += yi.w * cs.x - yr.w * cs.y;
        }
        *(float4*)&g_z[(size_t)bc * 1600 + kx * 20 + kyg] = zr;
        *(float4*)&g_z[(size_t)bc * 1600 + 800 + kx * 20 + kyg] = zi;
    }
}

// ---------------- per-mode complex channel mixing ----------------
__global__ void __launch_bounds__(256) k_mix(
    const float* __restrict__ sw1r, const float* __restrict__ sw1i,
    const float* __restrict__ sw2r, const float* __restrict__ sw2i, int layer)
{
    __shared__ __align__(16) float Wr[64 * 64], Wi[64 * 64]; // [i][o]
    __shared__ float Zr[16 * 64], Zi[16 * 64];
    int tid = threadIdx.x;
    int mode = blockIdx.x;
    int kxi = mode / 20, ky = mode % 20;
    const float* wr; const float* wi; int kxm;
    if (kxi < 20) { wr = sw1r; wi = sw1i; kxm = kxi; }
    else          { wr = sw2r; wi = sw2i; kxm = kxi - 20; }
    size_t base = (size_t)layer * 64 * 64 * 400 + (size_t)kxm * 20 + ky;
    for (int i = tid; i < 4096; i += 256) {
        size_t idx = base + (size_t)i * 400;
        Wr[i] = wr[idx]; Wi[i] = wi[idx];
    }
    int og = tid & 15, bb = tid >> 4;
    for (int pass = 0; pass < 2; pass++) {
        int b0 = pass * 16;
        __syncthreads();
        for (int i = tid; i < 1024; i += 256) {
            int lb = i >> 6, c = i & 63;
            size_t zb = ((size_t)(b0 + lb) * 64 + c) * 1600 + mode;
            Zr[i] = g_z[zb]; Zi[i] = g_z[zb + 800];
        }
        __syncthreads();
        float or0=0,or1=0,or2=0,or3=0, oi0=0,oi1=0,oi2=0,oi3=0;
#pragma unroll 8
        for (int i2 = 0; i2 < 64; i2++) {
            float zr = Zr[bb * 64 + i2], zi = Zi[bb * 64 + i2];
            float4 wr4 = *(const float4*)&Wr[i2 * 64 + og * 4];
            float4 wi4 = *(const float4*)&Wi[i2 * 64 + og * 4];
            or0 += zr * wr4.x - zi * wi4.x;  oi0 += zr * wi4.x + zi * wr4.x;
            or1 += zr * wr4.y - zi * wi4.y;  oi1 += zr * wi4.y + zi * wr4.y;
            or2 += zr * wr4.z - zi * wi4.z;  oi2 += zr * wi4.z + zi * wr4.z;
            or3 += zr * wr4.w - zi * wi4.w;  oi3 += zr * wi4.w + zi * wr4.w;
        }
        size_t ob = ((size_t)(b0 + bb) * 64 + og * 4) * 1600 + mode;
        g_zo[ob]        = or0;  g_zo[ob + 800]        = oi0;
        g_zo[ob + 1600] = or1;  g_zo[ob + 2400]       = oi1;
        g_zo[ob + 3200] = or2;  g_zo[ob + 4000]       = oi2;
        g_zo[ob + 4800] = or3;  g_zo[ob + 5600]       = oi3;
    }
}

// ---------------- inverse DFT along H ----------------
__global__ void __launch_bounds__(256) k_invH() {
    __shared__ __align__(16) float2 tw[40 * 130];
    __shared__ __align__(16) float zs[1600];
    int tid = threadIdx.x;
    int bo = blockIdx.x;
    for (int i = tid; i < 5120; i += 256) {
        int k = i >> 7, w = i & 127;
        tw[k * 130 + w] = make_float2(g_ThC[i], g_ThS[i]);
    }
    for (int i = tid; i < 1600; i += 256) zs[i] = g_zo[(size_t)bo * 1600 + i];
    __syncthreads();
    for (int u = tid; u < 640; u += 256) {
        int h = u / 5, kyg = (u % 5) * 4;
        float4 ur = {0,0,0,0}, ui = {0,0,0,0};
#pragma unroll 8
        for (int kx = 0; kx < 40; kx++) {
            float2 cs = tw[kx * 130 + h];
            float4 zr = *(const float4*)&zs[kx * 20 + kyg];
            float4 zi = *(const float4*)&zs[800 + kx * 20 + kyg];
            ur.x += zr.x * cs.x - zi.x * cs.y;  ui.x += zr.x * cs.y + zi.x * cs.x;
            ur.y += zr.y * cs.x - zi.y * cs.y;  ui.y += zr.y * cs.y + zi.y * cs.x;
            ur.z += zr.z * cs.x - zi.z * cs.y;  ui.z += zr.z * cs.y + zi.z * cs.x;
            ur.w += zr.w * cs.x - zi.w * cs.y;  ui.w += zr.w * cs.y + zi.w * cs.x;
        }
        *(float4*)&g_u[(size_t)bo * 5120 + h * 40 + kyg]      = ur;
        *(float4*)&g_u[(size_t)bo * 5120 + h * 40 + 20 + kyg] = ui;
    }
}

// ---------------- inverse rfft along W ----------------
__global__ void __launch_bounds__(256) k_invW() {
    __shared__ __align__(16) float us[5120];   // [h][40]
    __shared__ __align__(16) float tf[5120];   // [k][w]
    int tid = threadIdx.x;
    int bo = blockIdx.x;
    for (int i = tid; i < 5120; i += 256) {
        us[i] = g_u[(size_t)bo * 5120 + i];
        tf[i] = g_Tf[i];
    }
    __syncthreads();
    const float inv = 1.0f / 16384.0f;
    for (int u = tid; u < 2048; u += 256) {
        int hp = u >> 5, w4 = (u & 31) * 4;
        int h0 = hp * 2, h1 = h0 + 1;
        float4 a0 = {0,0,0,0}, a1 = {0,0,0,0};
#pragma unroll
        for (int ky = 1; ky < 20; ky++) {
            float ur0 = us[h0 * 40 + ky], ui0 = us[h0 * 40 + 20 + ky];
            float ur1 = us[h1 * 40 + ky], ui1 = us[h1 * 40 + 20 + ky];
            float4 c4 = *(const float4*)&tf[ky * 128 + w4];
            float4 s4 = *(const float4*)&tf[(20 + ky) * 128 + w4];
            a0.x += ur0 * c4.x + ui0 * s4.x;  a1.x += ur1 * c4.x + ui1 * s4.x;
            a0.y += ur0 * c4.y + ui0 * s4.y;  a1.y += ur1 * c4.y + ui1 * s4.y;
            a0.z += ur0 * c4.z + ui0 * s4.z;  a1.z += ur1 * c4.z + ui1 * s4.z;
            a0.w += ur0 * c4.w + ui0 * s4.w;  a1.w += ur1 * c4.w + ui1 * s4.w;
        }
        float dc0 = us[h0 * 40], dc1 = us[h1 * 40];
        float4 o0, o1;
        o0.x = (dc0 + 2.f * a0.x) * inv; o0.y = (dc0 + 2.f * a0.y) * inv;
        o0.z = (dc0 + 2.f * a0.z) * inv; o0.w = (dc0 + 2.f * a0.w) * inv;
        o1.x = (dc1 + 2.f * a1.x) * inv; o1.y = (dc1 + 2.f * a1.y) * inv;
        o1.z = (dc1 + 2.f * a1.z) * inv; o1.w = (dc1 + 2.f * a1.w) * inv;
        *(float4*)&g_x1[(size_t)bo * NPIX + h0 * 128 + w4] = o0;
        *(float4*)&g_x1[(size_t)bo * NPIX + h1 * 128 + w4] = o1;
    }
}

// ---------------- circular 3x3 conv: 32x32 tile, 16 outs (8 pairs), 4 px/thread ----------------
__global__ void __launch_bounds__(256) k_conv(
    const float* __restrict__ cw, const float* __restrict__ cb, int layer)
{
    __shared__ __align__(16) float tile[34 * 34];
    __shared__ __align__(16) float wsh[576 * 16];   // [cin*9+k][oc]
    int tid = threadIdx.x;
    int tx = tid & 31, ty = tid >> 5;
    int bz = blockIdx.z;
    int b = bz >> 2, ocg = bz & 3;
    int h0 = blockIdx.y * 32, w0 = blockIdx.x * 32;

    const float* cwp = cw + ((size_t)layer * 64 + ocg * 16) * 576;
    for (int i = tid; i < 9216; i += 256) {
        int oc = i / 576, r = i - oc * 576;
        wsh[r * 16 + oc] = cwp[(size_t)oc * 576 + r];
    }
    u64 acc2[4][8];
    const float* cbp = cb + layer * 64 + ocg * 16;
#pragma unroll
    for (int q = 0; q < 8; q++) {
        u64 v = pk(cbp[2 * q], cbp[2 * q + 1]);
#pragma unroll
        for (int p = 0; p < 4; p++) acc2[p][q] = v;
    }
    const float* xin = g_x + (size_t)b * 64 * NPIX;
    for (int cin = 0; cin < 64; cin++) {
        __syncthreads();
        for (int i = tid; i < 1156; i += 256) {
            int r = i / 34, c = i - r * 34;
            tile[i] = xin[(size_t)cin * NPIX + (((h0 + r - 1) & 127) << 7) + ((w0 + c - 1) & 127)];
        }
        __syncthreads();
        const float* wrow = &wsh[cin * 144];
#pragma unroll
        for (int k = 0; k < 9; k++) {
            int dy = k / 3, dx = k - dy * 3;
            ulonglong2 wA = *(const ulonglong2*)&wrow[k * 16];
            ulonglong2 wB = *(const ulonglong2*)&wrow[k * 16 + 4];
            ulonglong2 wC = *(const ulonglong2*)&wrow[k * 16 + 8];
            ulonglong2 wD = *(const ulonglong2*)&wrow[k * 16 + 12];
#pragma unroll
            for (int p = 0; p < 4; p++) {
                u64 v2 = pk2(tile[(ty + p * 8 + dy) * 34 + tx + dx]);
                fma2(acc2[p][0], wA.x, v2); fma2(acc2[p][1], wA.y, v2);
                fma2(acc2[p][2], wB.x, v2); fma2(acc2[p][3], wB.y, v2);
                fma2(acc2[p][4], wC.x, v2); fma2(acc2[p][5], wC.y, v2);
                fma2(acc2[p][6], wD.x, v2); fma2(acc2[p][7], wD.y, v2);
            }
        }
    }
    size_t obase = ((size_t)b * 64 + ocg * 16) * NPIX + (size_t)(h0 + ty) * 128 + w0 + tx;
#pragma unroll
    for (int p = 0; p < 4; p++) {
        size_t rb = obase + (size_t)(p * 8) * 128;
#pragma unroll
        for (int q = 0; q < 8; q++) {
            float lo, hi; unpk(acc2[p][q], lo, hi);
            g_x2[rb + (size_t)(2 * q) * NPIX]     = lo;
            g_x2[rb + (size_t)(2 * q + 1) * NPIX] = hi;
        }
    }
}

// ---------------- products + pointwise mix + tanh residual ----------------
// 256 threads: 128 pixel-slots x 2 halves of outputs; each thread: 2 px, 32 outs (16 pairs)
__global__ void __launch_bounds__(256) k_combine(
    const float* __restrict__ pw, const float* __restrict__ pb, int layer)
{
    __shared__ __align__(16) float wst[130 * 68];  // [c][o], pad 68
    __shared__ float bs[64];
    int tid = threadIdx.x;
    for (int i = tid; i < 8320; i += 256) {
        int o = i / 130, c = i - o * 130;
        wst[c * 68 + o] = pw[(size_t)layer * 8320 + i];
    }
    if (tid < 64) bs[tid] = pb[layer * 64 + tid];
    __syncthreads();
    int po = tid & 127, oh = tid >> 7, ob = oh * 32;
    int p0 = blockIdx.x * 256 + po;
    int b = p0 >> 14, pix0 = p0 & 16383;
    const float* x1p = g_x1 + ((size_t)b * 64) * NPIX + pix0;
    const float* x2p = g_x2 + ((size_t)b * 64) * NPIX + pix0;
    u64 acc0[16], acc1[16];
#pragma unroll
    for (int q = 0; q < 16; q++) {
        u64 v = pk(bs[ob + 2 * q], bs[ob + 2 * q + 1]);
        acc0[q] = v; acc1[q] = v;
    }
#pragma unroll 4
    for (int c = 0; c < 64; c++) {
        u64 A0 = pk2(x1p[(size_t)c * NPIX]);
        u64 A1 = pk2(x1p[(size_t)c * NPIX + 128]);
        u64 D0 = pk2(x2p[(size_t)c * NPIX]);
        u64 D1 = pk2(x2p[(size_t)c * NPIX + 128]);
        const float* wa = &wst[c * 68 + ob];
        const float* wd = &wst[(64 + c) * 68 + ob];
#pragma unroll
        for (int q8 = 0; q8 < 8; q8++) {
            ulonglong2 wva = *(const ulonglong2*)&wa[q8 * 4];
            fma2(acc0[q8 * 2],     wva.x, A0); fma2(acc0[q8 * 2 + 1], wva.y, A0);
            fma2(acc1[q8 * 2],     wva.x, A1); fma2(acc1[q8 * 2 + 1], wva.y, A1);
            ulonglong2 wvd = *(const ulonglong2*)&wd[q8 * 4];
            fma2(acc0[q8 * 2],     wvd.x, D0); fma2(acc0[q8 * 2 + 1], wvd.y, D0);
            fma2(acc1[q8 * 2],     wvd.x, D1); fma2(acc1[q8 * 2 + 1], wvd.y, D1);
        }
    }
    // product features: channels 0..3 of x1
    float p00 = x1p[0] * x1p[(size_t)2 * NPIX];
    float p01 = x1p[(size_t)1 * NPIX] * x1p[(size_t)3 * NPIX];
    float p10 = x1p[128] * x1p[(size_t)2 * NPIX + 128];
    float p11 = x1p[(size_t)1 * NPIX + 128] * x1p[(size_t)3 * NPIX + 128];
    {
        u64 P00 = pk2(p00), P01 = pk2(p01), P10 = pk2(p10), P11 = pk2(p11);
        const float* w0r = &wst[128 * 68 + ob];
        const float* w1r = &wst[129 * 68 + ob];
#pragma unroll
        for (int q8 = 0; q8 < 8; q8++) {
            ulonglong2 w0v = *(const ulonglong2*)&w0r[q8 * 4];
            ulonglong2 w1v = *(const ulonglong2*)&w1r[q8 * 4];
            fma2(acc0[q8 * 2],     w0v.x, P00); fma2(acc0[q8 * 2 + 1], w0v.y, P00);
            fma2(acc0[q8 * 2],     w1v.x, P01); fma2(acc0[q8 * 2 + 1], w1v.y, P01);
            fma2(acc1[q8 * 2],     w0v.x, P10); fma2(acc1[q8 * 2 + 1], w0v.y, P10);
            fma2(acc1[q8 * 2],     w1v.x, P11); fma2(acc1[q8 * 2 + 1], w1v.y, P11);
        }
    }
    float* xp = g_x + ((size_t)b * 64 + ob) * NPIX + pix0;
#pragma unroll
    for (int q = 0; q < 16; q++) {
        float lo, hi;
        unpk(acc0[q], lo, hi);
        xp[(size_t)(2 * q) * NPIX]           += tanhf(lo);
        xp[(size_t)(2 * q + 1) * NPIX]       += tanhf(hi);
        unpk(acc1[q], lo, hi);
        xp[(size_t)(2 * q) * NPIX + 128]     += tanhf(lo);
        xp[(size_t)(2 * q + 1) * NPIX + 128] += tanhf(hi);
    }
}

// ---------------- final projection MLP (packed over channel pairs) ----------------
__global__ void __launch_bounds__(128) k_final(
    const float* __restrict__ w1, const float* __restrict__ b1,
    const float* __restrict__ w2, const float* __restrict__ b2,
    float* __restrict__ out)
{
    __shared__ __align__(16) float w1s[128 * 64];
    __shared__ float b1s[128], w2s[128];
    int tid = threadIdx.x;
    for (int i = tid; i < 8192; i += 128) w1s[i] = w1[i];
    b1s[tid] = b1[tid];
    w2s[tid] = w2[tid];
    __syncthreads();
    int p = blockIdx.x * 128 + tid;
    int b = p >> 14, pix = p & 16383;
    const float* xp = g_x + ((size_t)b * 64) * NPIX + pix;
    u64 xv2[32];
#pragma unroll
    for (int c = 0; c < 32; c++)
        xv2[c] = pk(xp[(size_t)(2 * c) * NPIX], xp[(size_t)(2 * c + 1) * NPIX]);
    float acc = b2[0];
    for (int m = 0; m < 128; m++) {
        u64 a0 = pk(0.f, 0.f), a1 = a0, a2 = a0, a3 = a0;
        const float* wr = &w1s[m * 64];
#pragma unroll
        for (int q = 0; q < 16; q++) {
            ulonglong2 wv = *(const ulonglong2*)&wr[q * 4];
            if ((q & 3) == 0) { fma2(a0, wv.x, xv2[q * 2]); fma2(a1, wv.y, xv2[q * 2 + 1]); }
            else if ((q & 3) == 1) { fma2(a2, wv.x, xv2[q * 2]); fma2(a3, wv.y, xv2[q * 2 + 1]); }
            else if ((q & 3) == 2) { fma2(a0, wv.x, xv2[q * 2]); fma2(a1, wv.y, xv2[q * 2 + 1]); }
            else { fma2(a2, wv.x, xv2[q * 2]); fma2(a3, wv.y, xv2[q * 2 + 1]); }
        }
        float l0, h0, l1, h1, l2, h2, l3, h3;
        unpk(a0, l0, h0); unpk(a1, l1, h1); unpk(a2, l2, h2); unpk(a3, l3, h3);
        float t = b1s[m] + ((l0 + h0) + (l1 + h1)) + ((l2 + h2) + (l3 + h3));
        acc += w2s[m] * gelu_t(t);
    }
    out[p] = acc;
}

// ---------------- launch ----------------
extern "C" void kernel_launch(void* const* d_in, const int* in_sizes, int n_in,
                              void* d_out, int out_size)
{
    const float* x      = (const float*)d_in[0];
    const float* qa     = (const float*)d_in[1];
    const float* qb     = (const float*)d_in[2];
    const float* fc0_w1 = (const float*)d_in[3];
    const float* fc0_b1 = (const float*)d_in[4];
    const float* fc0_w2 = (const float*)d_in[5];
    const float* fc0_b2 = (const float*)d_in[6];
    const float* sw1r   = (const float*)d_in[7];
    const float* sw1i   = (const float*)d_in[8];
    const float* sw2r   = (const float*)d_in[9];
    const float* sw2i   = (const float*)d_in[10];
    const float* cw     = (const float*)d_in[11];
    const float* cb     = (const float*)d_in[12];
    const float* pw     = (const float*)d_in[13];
    const float* pb     = (const float*)d_in[14];
    const float* fc1_w1 = (const float*)d_in[15];
    const float* fc1_b1 = (const float*)d_in[16];
    const float* fc1_w2 = (const float*)d_in[17];
    const float* fc1_b2 = (const float*)d_in[18];
    float* out = (float*)d_out;

    k_init_tables<<<20, 256>>>();
    k_lift<<<4096, 128>>>(x, qa, qb, fc0_w1, fc0_b1, fc0_w2, fc0_b2);

    for (int layer = 0; layer < 4; layer++) {
        k_fwdW<<<8192, 160>>>();
        k_fwdH<<<2048, 256>>>();
        k_mix<<<800, 256>>>(sw1r, sw1i, sw2r, sw2i, layer);
        k_invH<<<2048, 256>>>();
        k_invW<<<2048, 256>>>();
        k_conv<<<dim3(4, 4, 128), 256>>>(cw, cb, layer);
        k_combine<<<2048, 256>>>(pw, pb, layer);
    }

    k_final<<<4096, 128>>>(fc1_w1, fc1_b1, fc1_w2, fc1_b2, out);
}